// round 9
// baseline (speedup 1.0000x reference)
#include <cuda_runtime.h>
#include <math.h>

#define NMOL 16
#define NATOM 64
#define RADF 64
#define ANGF 320
#define FEAT 384
#define RCR 5.2f
#define RCA 3.5f
#define FULL 0xffffffffu

__constant__ int c_triu16[16] = {
    0,1,2,3,
    1,4,5,6,
    2,5,7,8,
    3,6,8,9
};
// cos/sin of SHF_Z[z] = pi/16*(1+2z)
__constant__ float c_cz[8] = {
     0.980785280403230449f,  0.831469612302545237f,  0.555570233019602225f,
     0.195090322016128268f, -0.195090322016128268f, -0.555570233019602225f,
    -0.831469612302545237f, -0.980785280403230449f
};
__constant__ float c_sz[8] = {
     0.195090322016128268f,  0.555570233019602225f,  0.831469612302545237f,
     0.980785280403230449f,  0.980785280403230449f,  0.831469612302545237f,
     0.555570233019602225f,  0.195090322016128268f
};

__device__ __forceinline__ float pow32(float u) {
    u = fmaxf(u, 0.0f);
    u = u * u; u = u * u; u = u * u; u = u * u; u = u * u;
    return u;
}

__global__ __launch_bounds__(64)
void aev_kernel(const int* __restrict__ species,
                const float* __restrict__ coords,
                float* __restrict__ out,
                int aev_base, int write_species)
{
    const int w    = threadIdx.x >> 5;            // warp in block (0/1)
    const int lane = threadIdx.x & 31;
    const int atom = blockIdx.x * 2 + w;          // 0..1023
    const int n = atom >> 6;
    const int i = atom & 63;

    // warp-private shared state
    __shared__ float4 sA1[2][64];                 // dx,dy,dz,d  (angular list)
    __shared__ float4 sA2[2][64];                 // rinv, g=sqrt2*fca, -, -
    __shared__ int    sAs[2][64];                 // species     (angular list)
    __shared__ float2 sRL[2][64];                 // d, 0.25*fcr (radial list)
    __shared__ int    sRS[2][64];                 // species     (radial list)
    __shared__ float  sBA[2][ANGF];               // angular accum buf A
    __shared__ float  sBB[2][ANGF];               // angular accum buf B

    // ---- load molecule: lane holds atoms j=lane and j2=lane+32 ----
    const float* cb = coords + (size_t)n * NATOM * 3;
    const float x1 = cb[lane * 3 + 0];
    const float y1 = cb[lane * 3 + 1];
    const float z1 = cb[lane * 3 + 2];
    const float x2 = cb[(lane + 32) * 3 + 0];
    const float y2 = cb[(lane + 32) * 3 + 1];
    const float z2 = cb[(lane + 32) * 3 + 2];
    const int   sp1 = species[n * NATOM + lane];
    const int   sp2 = species[n * NATOM + lane + 32];

    // center coords + species (broadcast from owning lane; shfl executed by ALL lanes)
    const bool ilo = (i < 32);
    const float xi = __shfl_sync(FULL, ilo ? x1 : x2, i & 31);
    const float yi = __shfl_sync(FULL, ilo ? y1 : y2, i & 31);
    const float zi = __shfl_sync(FULL, ilo ? z1 : z2, i & 31);
    const int   si = __shfl_sync(FULL, ilo ? sp1 : sp2, i & 31);

    // ---- geometry for both halves ----
    const float dxl = x1 - xi, dyl = y1 - yi, dzl = z1 - zi;
    const float dxh = x2 - xi, dyh = y2 - yi, dzh = z2 - zi;
    const float d2l = fmaxf(dxl*dxl + dyl*dyl + dzl*dzl, 1e-20f);
    const float d2h = fmaxf(dxh*dxh + dyh*dyh + dzh*dzh, 1e-20f);
    const float rl = rsqrtf(d2l), rh = rsqrtf(d2h);
    const float dl = d2l * rl,    dh = d2h * rh;

    const bool selfl = (lane == i);
    const bool selfh = (lane + 32 == i);
    const bool vRl = !selfl && (dl <= RCR);
    const bool vRh = !selfh && (dh <= RCR);
    const bool vAl = !selfl && (dl <= RCA);
    const bool vAh = !selfh && (dh <= RCA);

    const float PIA = (float)M_PI / RCA, PIR = (float)M_PI / RCR;
    const float fcal = 0.5f * __cosf(PIA * dl) + 0.5f;
    const float fcah = 0.5f * __cosf(PIA * dh) + 0.5f;
    const float hrl  = 0.25f * (0.5f * __cosf(PIR * dl) + 0.5f);
    const float hrh  = 0.25f * (0.5f * __cosf(PIR * dh) + 0.5f);

    const unsigned lt = (1u << lane) - 1u;
    const unsigned mRl = __ballot_sync(FULL, vRl);
    const unsigned mRh = __ballot_sync(FULL, vRh);
    const unsigned mAl = __ballot_sync(FULL, vAl);
    const unsigned mAh = __ballot_sync(FULL, vAh);

    // ---- compact lists (warp-private, deterministic order) ----
    if (vRl) { int q = __popc(mRl & lt);
        sRL[w][q] = make_float2(dl, hrl); sRS[w][q] = sp1; }
    if (vRh) { int q = __popc(mRl) + __popc(mRh & lt);
        sRL[w][q] = make_float2(dh, hrh); sRS[w][q] = sp2; }
    if (vAl) { int q = __popc(mAl & lt);
        sA1[w][q] = make_float4(dxl, dyl, dzl, dl);
        sA2[w][q] = make_float4(rl, 1.41421356237f * fcal, 0.f, 0.f);
        sAs[w][q] = sp1; }
    if (vAh) { int q = __popc(mAl) + __popc(mAh & lt);
        sA1[w][q] = make_float4(dxh, dyh, dzh, dh);
        sA2[w][q] = make_float4(rh, 1.41421356237f * fcah, 0.f, 0.f);
        sAs[w][q] = sp2; }

    // zero angular buffers
    #pragma unroll
    for (int t = 0; t < 10; t++) {
        sBA[w][t * 32 + lane] = 0.0f;
        sBB[w][t * 32 + lane] = 0.0f;
    }
    __syncwarp();

    const int m_r = __popc(mRl) + __popc(mRh);
    const int m_a = __popc(mAl) + __popc(mAh);

    // ---- radial: lane owns feature (r = lane&15, species halves) ----
    const float shf = 0.9f + 0.26875f * (float)(lane & 15);
    const int   s0  = lane >> 4;                  // 0 or 1
    float acc0 = 0.0f, acc1 = 0.0f;
    for (int q = 0; q < m_r; q++) {
        const float2 df = sRL[w][q];
        const int    s  = sRS[w][q];
        const float t = df.x - shf;
        const float e = __expf(-16.0f * t * t) * df.y;
        if (s == s0)     acc0 += e;
        if (s == s0 + 2) acc1 += e;
    }

    // ---- angular: lane owns feature (a = lane>>3, z = lane&7) ----
    const float sha = 0.9f + 0.65f * (float)(lane >> 3);
    const float cz = c_cz[lane & 7], sz = c_sz[lane & 7];
    const int npairs = m_a * (m_a - 1) / 2;
    float* bufA = &sBA[w][0];
    float* bufB = &sBB[w][0];

    int jj = 0, kk = 1;
    int p = 0;
    for (; p + 1 < npairs; p += 2) {
        // pair 0 -> bufA
        {
            const float4 Pj = sA1[w][jj], Qj = sA2[w][jj];
            const float4 Pk = sA1[w][kk], Qk = sA2[w][kk];
            const int pidx = c_triu16[sAs[w][jj] * 4 + sAs[w][kk]];
            const float dot = Pj.x*Pk.x + Pj.y*Pk.y + Pj.z*Pk.z;
            float c = 0.95f * dot * Qj.x * Qk.x;
            c = fminf(0.95f, fmaxf(-0.95f, c));
            const float s = sqrtf(1.0f - c * c);
            const float base = Qj.y * Qk.y;
            const float davg = 0.5f * (Pj.w + Pk.w);
            const float t  = davg - sha;
            const float f2 = __expf(-8.0f * t * t);
            const float f1 = pow32(0.5f * (1.0f + c * cz + s * sz));
            bufA[pidx * 32 + lane] += base * f2 * f1;
        }
        if (++kk == m_a) { ++jj; kk = jj + 1; }
        // pair 1 -> bufB (independent RMW chain)
        {
            const float4 Pj = sA1[w][jj], Qj = sA2[w][jj];
            const float4 Pk = sA1[w][kk], Qk = sA2[w][kk];
            const int pidx = c_triu16[sAs[w][jj] * 4 + sAs[w][kk]];
            const float dot = Pj.x*Pk.x + Pj.y*Pk.y + Pj.z*Pk.z;
            float c = 0.95f * dot * Qj.x * Qk.x;
            c = fminf(0.95f, fmaxf(-0.95f, c));
            const float s = sqrtf(1.0f - c * c);
            const float base = Qj.y * Qk.y;
            const float davg = 0.5f * (Pj.w + Pk.w);
            const float t  = davg - sha;
            const float f2 = __expf(-8.0f * t * t);
            const float f1 = pow32(0.5f * (1.0f + c * cz + s * sz));
            bufB[pidx * 32 + lane] += base * f2 * f1;
        }
        if (++kk == m_a) { ++jj; kk = jj + 1; }
    }
    if (p < npairs) {
        const float4 Pj = sA1[w][jj], Qj = sA2[w][jj];
        const float4 Pk = sA1[w][kk], Qk = sA2[w][kk];
        const int pidx = c_triu16[sAs[w][jj] * 4 + sAs[w][kk]];
        const float dot = Pj.x*Pk.x + Pj.y*Pk.y + Pj.z*Pk.z;
        float c = 0.95f * dot * Qj.x * Qk.x;
        c = fminf(0.95f, fmaxf(-0.95f, c));
        const float s = sqrtf(1.0f - c * c);
        const float base = Qj.y * Qk.y;
        const float davg = 0.5f * (Pj.w + Pk.w);
        const float t  = davg - sha;
        const float f2 = __expf(-8.0f * t * t);
        const float f1 = pow32(0.5f * (1.0f + c * cz + s * sz));
        bufA[pidx * 32 + lane] += base * f2 * f1;
    }
    __syncwarp();

    // ---- write out ----
    float* ob = out + aev_base + (size_t)atom * FEAT;
    ob[lane]      = acc0;
    ob[lane + 32] = acc1;
    #pragma unroll
    for (int t = 0; t < 10; t++) {
        ob[RADF + t * 32 + lane] = bufA[t * 32 + lane] + bufB[t * 32 + lane];
    }
    if (write_species && lane == 0) {
        out[atom] = (float)si;
    }
}

extern "C" void kernel_launch(void* const* d_in, const int* in_sizes, int n_in,
                              void* d_out, int out_size)
{
    const int*   species = (const int*)d_in[0];
    const float* coords  = (const float*)d_in[1];
    float* out = (float*)d_out;

    const int total_atoms = NMOL * NATOM;       // 1024
    int aev_base = 0, write_species = 0;
    if (out_size >= total_atoms * FEAT + total_atoms) {
        aev_base = total_atoms;
        write_species = 1;
    }

    aev_kernel<<<total_atoms / 2, 64>>>(species, coords, out, aev_base, write_species);
}

// round 10
// speedup vs baseline: 1.1392x; 1.1392x over previous
#include <cuda_runtime.h>
#include <math.h>

#define NMOL 16
#define NATOM 64
#define RADF 64
#define ANGF 320
#define FEAT 384
#define RCR 5.2f
#define RCA 3.5f
#define FULL 0xffffffffu
#define TPB 128
#define NW 4            // warps per block
#define RG 8            // radial groups

__constant__ int c_triu16[16] = {
    0,1,2,3,
    1,4,5,6,
    2,5,7,8,
    3,6,8,9
};
// cos/sin of SHF_Z[z] = pi/16*(1+2z)
__constant__ float c_cz[8] = {
     0.980785280403230449f,  0.831469612302545237f,  0.555570233019602225f,
     0.195090322016128268f, -0.195090322016128268f, -0.555570233019602225f,
    -0.831469612302545237f, -0.980785280403230449f
};
__constant__ float c_sz[8] = {
     0.195090322016128268f,  0.555570233019602225f,  0.831469612302545237f,
     0.980785280403230449f,  0.980785280403230449f,  0.831469612302545237f,
     0.555570233019602225f,  0.195090322016128268f
};

__device__ __forceinline__ float pow32(float u) {
    u = fmaxf(u, 0.0f);
    u = u * u; u = u * u; u = u * u; u = u * u; u = u * u;
    return u;
}

__global__ __launch_bounds__(TPB)
void aev_kernel(const int* __restrict__ species,
                const float* __restrict__ coords,
                float* __restrict__ out,
                int aev_base, int write_species)
{
    const int atom = blockIdx.x;          // 0..1023
    const int n = atom >> 6;
    const int i = atom & 63;
    const int tid  = threadIdx.x;
    const int lane = tid & 31;
    const int w    = tid >> 5;

    __shared__ float4 sA1[NATOM];         // dx,dy,dz,d        (angular list)
    __shared__ float2 sA2[NATOM];         // rinv, sqrt2*fca   (angular list)
    __shared__ int    sAs[NATOM];         // species           (angular list)
    __shared__ float2 sRL[NATOM];         // d, 0.25*fcr       (radial list)
    __shared__ int    sRS[NATOM];         // species           (radial list)
    __shared__ int    sM[2];              // m_r, m_a
    __shared__ float  pR[RG * 65];        // radial partials (padded pitch 65)
    __shared__ float  pA[NW * ANGF];      // angular partials

    // ================= phase 1: warp 0 builds compacted lists =================
    if (w == 0) {
        const float* cb = coords + (size_t)n * NATOM * 3;
        const float x1 = cb[lane * 3 + 0];
        const float y1 = cb[lane * 3 + 1];
        const float z1 = cb[lane * 3 + 2];
        const float x2 = cb[(lane + 32) * 3 + 0];
        const float y2 = cb[(lane + 32) * 3 + 1];
        const float z2 = cb[(lane + 32) * 3 + 2];
        const int   sp1 = species[n * NATOM + lane];
        const int   sp2 = species[n * NATOM + lane + 32];

        const bool ilo = (i < 32);
        const float xi = __shfl_sync(FULL, ilo ? x1 : x2, i & 31);
        const float yi = __shfl_sync(FULL, ilo ? y1 : y2, i & 31);
        const float zi = __shfl_sync(FULL, ilo ? z1 : z2, i & 31);
        const int   si = __shfl_sync(FULL, ilo ? sp1 : sp2, i & 31);

        const float dxl = x1 - xi, dyl = y1 - yi, dzl = z1 - zi;
        const float dxh = x2 - xi, dyh = y2 - yi, dzh = z2 - zi;
        const float d2l = fmaxf(dxl*dxl + dyl*dyl + dzl*dzl, 1e-20f);
        const float d2h = fmaxf(dxh*dxh + dyh*dyh + dzh*dzh, 1e-20f);
        const float rl = rsqrtf(d2l), rh = rsqrtf(d2h);
        const float dl = d2l * rl,    dh = d2h * rh;

        const bool selfl = (lane == i);
        const bool selfh = (lane + 32 == i);
        const bool vRl = !selfl && (dl <= RCR);
        const bool vRh = !selfh && (dh <= RCR);
        const bool vAl = !selfl && (dl <= RCA);
        const bool vAh = !selfh && (dh <= RCA);

        const float PIA = (float)M_PI / RCA, PIR = (float)M_PI / RCR;
        const float fcal = 0.5f * __cosf(PIA * dl) + 0.5f;
        const float fcah = 0.5f * __cosf(PIA * dh) + 0.5f;
        const float hrl  = 0.25f * (0.5f * __cosf(PIR * dl) + 0.5f);
        const float hrh  = 0.25f * (0.5f * __cosf(PIR * dh) + 0.5f);

        const unsigned lt  = (1u << lane) - 1u;
        const unsigned mRl = __ballot_sync(FULL, vRl);
        const unsigned mRh = __ballot_sync(FULL, vRh);
        const unsigned mAl = __ballot_sync(FULL, vAl);
        const unsigned mAh = __ballot_sync(FULL, vAh);

        if (vRl) { int q = __popc(mRl & lt);
            sRL[q] = make_float2(dl, hrl); sRS[q] = sp1; }
        if (vRh) { int q = __popc(mRl) + __popc(mRh & lt);
            sRL[q] = make_float2(dh, hrh); sRS[q] = sp2; }
        if (vAl) { int q = __popc(mAl & lt);
            sA1[q] = make_float4(dxl, dyl, dzl, dl);
            sA2[q] = make_float2(rl, 1.41421356237f * fcal);
            sAs[q] = sp1; }
        if (vAh) { int q = __popc(mAl) + __popc(mAh & lt);
            sA1[q] = make_float4(dxh, dyh, dzh, dh);
            sA2[q] = make_float2(rh, 1.41421356237f * fcah);
            sAs[q] = sp2; }

        if (lane == 0) {
            sM[0] = __popc(mRl) + __popc(mRh);
            sM[1] = __popc(mAl) + __popc(mAh);
            if (write_species) out[atom] = (float)si;
        }
    }
    __syncthreads();

    const int m_r = sM[0];
    const int m_a = sM[1];

    // ================= phase 2a: radial (register accum, no atomics) =========
    {
        const int r = tid & 15;
        const int g = tid >> 4;                    // 0..7
        const float shf = 0.9f + 0.26875f * (float)r;
        float a0 = 0.f, a1 = 0.f, a2 = 0.f, a3 = 0.f;
        for (int q = g; q < m_r; q += RG) {
            const float2 df = sRL[q];
            const int    s  = sRS[q];
            const float t = df.x - shf;
            const float e = __expf(-16.0f * t * t) * df.y;
            a0 += (s == 0) ? e : 0.f;
            a1 += (s == 1) ? e : 0.f;
            a2 += (s == 2) ? e : 0.f;
            a3 += (s == 3) ? e : 0.f;
        }
        pR[g * 65 +  0 + r] = a0;
        pR[g * 65 + 16 + r] = a1;
        pR[g * 65 + 32 + r] = a2;
        pR[g * 65 + 48 + r] = a3;
    }

    // ================= phase 2b: angular (register buckets, no atomics) ======
    {
        const float sha = 0.9f + 0.65f * (float)(lane >> 3);
        const float cz = c_cz[lane & 7], sz = c_sz[lane & 7];
        float acc[10];
        #pragma unroll
        for (int b = 0; b < 10; b++) acc[b] = 0.f;

        const int npairs = m_a * (m_a - 1) / 2;
        for (int p = w; p < npairs; p += NW) {
            // closed-form unordered-pair decode (reverse triangular)
            const int t_ = npairs - 1 - p;
            int K = (int)((__fsqrt_rn((float)(8 * t_ + 1)) - 1.0f) * 0.5f);
            K += ((K + 1) * (K + 2) / 2 <= t_) ? 1 : 0;
            K -= (K * (K + 1) / 2 > t_) ? 1 : 0;
            const int jj = m_a - 2 - K;
            const int kk = m_a - 1 - (t_ - K * (K + 1) / 2);

            const float4 Pj = sA1[jj]; const float2 Qj = sA2[jj];
            const float4 Pk = sA1[kk]; const float2 Qk = sA2[kk];
            const int pidx = c_triu16[sAs[jj] * 4 + sAs[kk]];

            const float dot = Pj.x * Pk.x + Pj.y * Pk.y + Pj.z * Pk.z;
            float c = 0.95f * dot * Qj.x * Qk.x;
            c = fminf(0.95f, fmaxf(-0.95f, c));
            const float s = sqrtf(1.0f - c * c);
            const float davg = 0.5f * (Pj.w + Pk.w);
            const float t2 = davg - sha;
            const float f2 = __expf(-8.0f * t2 * t2);
            const float f1 = pow32(0.5f * (1.0f + c * cz + s * sz));
            const float v  = Qj.y * Qk.y * f2 * f1;

            #pragma unroll
            for (int b = 0; b < 10; b++) acc[b] += (pidx == b) ? v : 0.f;
        }
        #pragma unroll
        for (int b = 0; b < 10; b++) pA[w * ANGF + b * 32 + lane] = acc[b];
    }
    __syncthreads();

    // ================= phase 3: reduce partials + write ======================
    float* ob = out + aev_base + (size_t)atom * FEAT;
    if (tid < RADF) {
        float sum = 0.f;
        #pragma unroll
        for (int g = 0; g < RG; g++) sum += pR[g * 65 + tid];
        ob[tid] = sum;
    }
    for (int f = tid; f < ANGF; f += TPB) {
        float sum = 0.f;
        #pragma unroll
        for (int ww = 0; ww < NW; ww++) sum += pA[ww * ANGF + f];
        ob[RADF + f] = sum;
    }
}

extern "C" void kernel_launch(void* const* d_in, const int* in_sizes, int n_in,
                              void* d_out, int out_size)
{
    const int*   species = (const int*)d_in[0];
    const float* coords  = (const float*)d_in[1];
    float* out = (float*)d_out;

    const int total_atoms = NMOL * NATOM;       // 1024
    int aev_base = 0, write_species = 0;
    if (out_size >= total_atoms * FEAT + total_atoms) {
        aev_base = total_atoms;
        write_species = 1;
    }

    aev_kernel<<<total_atoms, TPB>>>(species, coords, out, aev_base, write_species);
}

// round 11
// speedup vs baseline: 1.3393x; 1.1756x over previous
#include <cuda_runtime.h>
#include <math.h>

#define NMOL 16
#define NATOM 64
#define RADF 64
#define ANGF 320
#define FEAT 384
#define RCR 5.2f
#define RCA 3.5f
#define FULL 0xffffffffu
#define TPB 256

__constant__ int c_triu16[16] = {
    0,1,2,3,
    1,4,5,6,
    2,5,7,8,
    3,6,8,9
};
// cos/sin of SHF_Z[z] = pi/16*(1+2z)
__constant__ float c_cz[8] = {
     0.980785280403230449f,  0.831469612302545237f,  0.555570233019602225f,
     0.195090322016128268f, -0.195090322016128268f, -0.555570233019602225f,
    -0.831469612302545237f, -0.980785280403230449f
};
__constant__ float c_sz[8] = {
     0.195090322016128268f,  0.555570233019602225f,  0.831469612302545237f,
     0.980785280403230449f,  0.980785280403230449f,  0.831469612302545237f,
     0.555570233019602225f,  0.195090322016128268f
};

__device__ __forceinline__ float pow32(float u) {
    u = fmaxf(u, 0.0f);
    u = u * u; u = u * u; u = u * u; u = u * u; u = u * u;
    return u;
}

__global__ __launch_bounds__(TPB)
void aev_kernel(const int* __restrict__ species,
                const float* __restrict__ coords,
                float* __restrict__ out,
                int aev_base, int write_species)
{
    const int atom = blockIdx.x;          // 0..1023
    const int n = atom >> 6;
    const int i = atom & 63;
    const int tid  = threadIdx.x;
    const int lane = tid & 31;
    const int w    = tid >> 5;

    __shared__ float4 sP[NATOM];          // dx,dy,dz,d              (angular)
    __shared__ float4 sQ[NATOM];          // rinv, sqrt2*fca, spec, -(angular)
    __shared__ float4 sR[NATOM];          // d, 0.25*fcr, spec, -    (radial)
    __shared__ float  s_ang[ANGF];        // angular accumulators
    __shared__ float  pR[16 * 68];        // radial partials (pitch 68)
    __shared__ int    sW[4];              // per-warp counts: mR0,mA0,mR1,mA1

    // idle warps zero the angular accumulators during the prologue
    if (tid >= 64) {
        for (int f = tid - 64; f < ANGF; f += TPB - 64) s_ang[f] = 0.0f;
    }

    // ================= prologue: warps 0-1, thread = neighbor j ==============
    unsigned mR = 0, mA = 0;
    bool vR = false, vA = false;
    float dx = 0.f, dy = 0.f, dz = 0.f, d = 0.f, rinv = 0.f, fca = 0.f, hr = 0.f;
    int sp = 0;
    if (w < 2) {
        const float* cb = coords + (size_t)n * NATOM * 3;
        const int j = tid;                 // 0..63
        const float xj = cb[j * 3 + 0];
        const float yj = cb[j * 3 + 1];
        const float zj = cb[j * 3 + 2];
        const float xi = cb[i * 3 + 0];    // broadcast loads (same addr all lanes)
        const float yi = cb[i * 3 + 1];
        const float zi = cb[i * 3 + 2];
        sp = species[n * NATOM + j];

        dx = xj - xi; dy = yj - yi; dz = zj - zi;
        const float d2 = fmaxf(dx * dx + dy * dy + dz * dz, 1e-20f);
        rinv = rsqrtf(d2);
        d = d2 * rinv;

        const bool self = (j == i);
        vR = !self && (d <= RCR);
        vA = !self && (d <= RCA);

        const float PIA = (float)M_PI / RCA, PIR = (float)M_PI / RCR;
        fca = 0.5f * __cosf(PIA * d) + 0.5f;
        hr  = 0.25f * (0.5f * __cosf(PIR * d) + 0.5f);

        mR = __ballot_sync(FULL, vR);
        mA = __ballot_sync(FULL, vA);
        if (lane == 0) { sW[w * 2 + 0] = __popc(mR); sW[w * 2 + 1] = __popc(mA); }
        if (write_species && tid == 0) out[atom] = (float)species[n * NATOM + i];
    }
    __syncthreads();                       // counts visible

    if (w < 2) {
        const unsigned lt = (1u << lane) - 1u;
        const int baseR = (w == 1) ? sW[0] : 0;
        const int baseA = (w == 1) ? sW[1] : 0;
        if (vR) {
            const int q = baseR + __popc(mR & lt);
            sR[q] = make_float4(d, hr, __int_as_float(sp), 0.f);
        }
        if (vA) {
            const int q = baseA + __popc(mA & lt);
            sP[q] = make_float4(dx, dy, dz, d);
            sQ[q] = make_float4(rinv, 1.41421356237f * fca, __int_as_float(sp), 0.f);
        }
    }
    __syncthreads();                       // lists + zeroed s_ang ready

    const int m_r = sW[0] + sW[2];
    const int m_a = sW[1] + sW[3];

    // ================= radial: register accum, no atomics ====================
    {
        const int r = tid & 15;
        const int g = tid >> 4;            // 0..15
        const float shf = 0.9f + 0.26875f * (float)r;
        float a0 = 0.f, a1 = 0.f, a2 = 0.f, a3 = 0.f;
        for (int q = g; q < m_r; q += 16) {
            const float4 e = sR[q];
            const int s = __float_as_int(e.z);
            const float t = e.x - shf;
            const float v = __expf(-16.0f * t * t) * e.y;
            a0 += (s == 0) ? v : 0.f;
            a1 += (s == 1) ? v : 0.f;
            a2 += (s == 2) ? v : 0.f;
            a3 += (s == 3) ? v : 0.f;
        }
        pR[g * 68 +  0 + r] = a0;
        pR[g * 68 + 16 + r] = a1;
        pR[g * 68 + 32 + r] = a2;
        pR[g * 68 + 48 + r] = a3;
    }

    // ================= angular: warp-per-pair, lane = (a,z) feature ==========
    {
        const float sha = 0.9f + 0.65f * (float)(lane >> 3);
        const float cz = c_cz[lane & 7], sz = c_sz[lane & 7];
        const int npairs = m_a * (m_a - 1) / 2;
        for (int p = w; p < npairs; p += 8) {
            // closed-form unordered-pair decode (validated R10)
            const int t_ = npairs - 1 - p;
            int K = (int)((__fsqrt_rn((float)(8 * t_ + 1)) - 1.0f) * 0.5f);
            K += ((K + 1) * (K + 2) / 2 <= t_) ? 1 : 0;
            K -= (K * (K + 1) / 2 > t_) ? 1 : 0;
            const int jj = m_a - 2 - K;
            const int kk = m_a - 1 - (t_ - K * (K + 1) / 2);

            const float4 Pj = sP[jj], Qj = sQ[jj];
            const float4 Pk = sP[kk], Qk = sQ[kk];
            const int pidx = c_triu16[__float_as_int(Qj.z) * 4 + __float_as_int(Qk.z)];

            const float dot = Pj.x * Pk.x + Pj.y * Pk.y + Pj.z * Pk.z;
            float c = 0.95f * dot * Qj.x * Qk.x;
            c = fminf(0.95f, fmaxf(-0.95f, c));
            const float s = sqrtf(1.0f - c * c);
            const float davg = 0.5f * (Pj.w + Pk.w);
            const float t2 = davg - sha;
            const float f2 = __expf(-8.0f * t2 * t2);
            const float f1 = pow32(0.5f * (1.0f + c * cz + s * sz));
            atomicAdd(&s_ang[pidx * 32 + lane], Qj.y * Qk.y * f2 * f1);
        }
    }
    __syncthreads();

    // ================= epilogue: reduce radial partials + store ==============
    float* ob = out + aev_base + (size_t)atom * FEAT;
    if (tid < RADF) {
        float sum = 0.f;
        #pragma unroll
        for (int g = 0; g < 16; g++) sum += pR[g * 68 + tid];
        ob[tid] = sum;
    }
    for (int f = tid; f < ANGF; f += TPB) ob[RADF + f] = s_ang[f];
}

extern "C" void kernel_launch(void* const* d_in, const int* in_sizes, int n_in,
                              void* d_out, int out_size)
{
    const int*   species = (const int*)d_in[0];
    const float* coords  = (const float*)d_in[1];
    float* out = (float*)d_out;

    const int total_atoms = NMOL * NATOM;       // 1024
    int aev_base = 0, write_species = 0;
    if (out_size >= total_atoms * FEAT + total_atoms) {
        aev_base = total_atoms;
        write_species = 1;
    }

    aev_kernel<<<total_atoms, TPB>>>(species, coords, out, aev_base, write_species);
}